// round 13
// baseline (speedup 1.0000x reference)
#include <cuda_runtime.h>
#include <cuda_bf16.h>
#include <cstdint>

// ---------------- Problem constants ----------------
#define N_ROWS   131072      // 32*16*16*16
#define DIMK     256         // E_DIM
#define NCODE    512         // N_EMBED

// Output layout (concatenated flattened outputs, float32):
#define ZQ_OFF   0
#define VQ_OFF   33554432
#define CM_OFF   33554433
#define IDX_OFF  33554434
#define HIST_OFF 33685506

#define NBLK (N_ROWS / 128)       // 1024 main blocks
#define MARGIN 0.8f               // ~6 sigma of bf16 sim-error difference (proven)
#define CAND   12                 // candidate slots per row

// ---------------- Device scratch (no allocations allowed) ----------------
__device__ __align__(16) __nv_bfloat16 g_eb[NCODE * DIMK];  // bf16 embedding
__device__ float g_ce[NCODE];             // ||e_n||^2 (fp32, exact)
__device__ float g_part[NBLK];            // loss partials
__device__ unsigned g_ctr;                // completed-CTA counter (reset by k_prep)

// ---------------- PTX helpers (portable to compute_103) ----------------
__device__ __forceinline__ uint32_t smem_u32(const void* p) {
    uint32_t a;
    asm("{ .reg .u64 t; cvta.to.shared.u64 t, %1; cvt.u32.u64 %0, t; }" : "=r"(a) : "l"(p));
    return a;
}
#define CP_ASYNC16(dst, src) \
    asm volatile("cp.async.cg.shared.global [%0], [%1], 16;" :: "r"(dst), "l"(src) : "memory")
#define CP_COMMIT() asm volatile("cp.async.commit_group;" ::: "memory")
#define CP_WAIT0()  asm volatile("cp.async.wait_group 0;" ::: "memory")
#define LDSM4(r0, r1, r2, r3, addr) \
    asm volatile("ldmatrix.sync.aligned.m8n8.x4.shared.b16 {%0,%1,%2,%3}, [%4];" \
        : "=r"(r0), "=r"(r1), "=r"(r2), "=r"(r3) : "r"(addr))
#define MMA16816(d, a, b0, b1) \
    asm volatile("mma.sync.aligned.m16n8k16.row.col.f32.bf16.bf16.f32 " \
        "{%0,%1,%2,%3},{%4,%5,%6,%7},{%8,%9},{%0,%1,%2,%3};" \
        : "+f"((d)[0]), "+f"((d)[1]), "+f"((d)[2]), "+f"((d)[3]) \
        : "r"((a)[0]), "r"((a)[1]), "r"((a)[2]), "r"((a)[3]), "r"(b0), "r"(b1))

// Monotone float<->uint map for atomicMax on floats
__device__ __forceinline__ unsigned fmono(float x) {
    unsigned u = __float_as_uint(x);
    return (u & 0x80000000u) ? ~u : (u | 0x80000000u);
}
__device__ __forceinline__ float funmono(unsigned u) {
    return (u & 0x80000000u) ? __uint_as_float(u ^ 0x80000000u) : __uint_as_float(~u);
}

// ---------------- SMEM layout (identical to R10) ----------------
#define RS 528                    // bf16 row pitch (264 bf16): conflict-reduced ldmatrix
#define SM_CE   0                 // 512 f32 = 2048B
#define SM_RB   2048              // 128 u32
#define SM_CNT  2560              // 128 s32
#define SM_CAND 3072              // 128 * 12 s32 = 6144
#define SM_A    9216              // 128 * 528 = 67584
#define SM_B0   76800             // 128 * 528
#define SM_B1   144384            // 128 * 528
#define SMEM_BYTES 211968

// ---------------- Kernel: prep (convert emb, norms, zero hist/ctr) ----------------
__global__ void k_prep(const float* __restrict__ emb, float* __restrict__ out) {
    int n = blockIdx.x;               // 512 blocks, 64 threads
    int t = threadIdx.x;
    float4 v = *(const float4*)(emb + (size_t)n * DIMK + t * 4);
    __nv_bfloat162 p0 = __floats2bfloat162_rn(v.x, v.y);
    __nv_bfloat162 p1 = __floats2bfloat162_rn(v.z, v.w);
    uint2 w;
    w.x = *(unsigned*)&p0;
    w.y = *(unsigned*)&p1;
    *(uint2*)((char*)g_eb + (size_t)n * 512 + t * 8) = w;
    float s = v.x * v.x + v.y * v.y + v.z * v.z + v.w * v.w;
    #pragma unroll
    for (int o = 16; o > 0; o >>= 1) s += __shfl_down_sync(0xffffffffu, s, o);
    __shared__ float ws[2];
    if ((t & 31) == 0) ws[t >> 5] = s;
    __syncthreads();
    if (t == 0) g_ce[n] = ws[0] + ws[1];
    if (n == 0) {
        #pragma unroll
        for (int k = 0; k < 8; k++) out[HIST_OFF + t + k * 64] = 0.0f;
        if (t == 0) g_ctr = 0u;
    }
}

// ---------------- Kernel: HMMA GEMM (16 warps) + candidates + fused epilogue + final ----------------
__global__ __launch_bounds__(512, 1)
void k_mma(const float* __restrict__ z, const float* __restrict__ emb,
           float* __restrict__ out) {
    extern __shared__ __align__(128) unsigned char smem[];
    float*    ceS     = (float*)(smem + SM_CE);
    unsigned* rowBest = (unsigned*)(smem + SM_RB);
    int*      sCnt    = (int*)(smem + SM_CNT);
    int*      sCand   = (int*)(smem + SM_CAND);
    uint32_t sbase = smem_u32(smem);
    uint32_t sA  = sbase + SM_A;
    uint32_t sB[2] = { sbase + SM_B0, sbase + SM_B1 };

    int tid = threadIdx.x, lane = tid & 31, wid = tid >> 5;
    int wm = wid & 3;        // M block: 32 rows
    int wn = wid >> 2;       // N block: 32 cols (4 groups cover 128-col chunk)
    int rowBase = blockIdx.x * 128;

    if (tid < NCODE) ceS[tid] = g_ce[tid];
    if (tid < 128) { rowBest[tid] = 0u; sCnt[tid] = 0; }

    // ---- prefetch B chunk 0 (128 rows x 32 16B-units) ----
    {
        const char* src = (const char*)g_eb;
        #pragma unroll
        for (int it = 0; it < 8; it++) {
            int t = tid + it * 512;
            int r = t >> 5, c = t & 31;
            CP_ASYNC16(sB[0] + r * RS + c * 16, src + r * 512 + c * 16);
        }
        CP_COMMIT();
    }

    // ---- load + convert A tile: 128 rows x 256 fp32 -> bf16, padded rows ----
    #pragma unroll
    for (int it = 0; it < 8; it++) {
        int t = tid + it * 512;
        int r = t >> 5, c = t & 31;
        const float4* zp = (const float4*)(z + (size_t)(rowBase + r) * DIMK + c * 8);
        float4 u0 = zp[0], u1 = zp[1];
        __nv_bfloat162 p0 = __floats2bfloat162_rn(u0.x, u0.y);
        __nv_bfloat162 p1 = __floats2bfloat162_rn(u0.z, u0.w);
        __nv_bfloat162 p2 = __floats2bfloat162_rn(u1.x, u1.y);
        __nv_bfloat162 p3 = __floats2bfloat162_rn(u1.z, u1.w);
        uint4 w;
        w.x = *(unsigned*)&p0; w.y = *(unsigned*)&p1;
        w.z = *(unsigned*)&p2; w.w = *(unsigned*)&p3;
        *(uint4*)(smem + SM_A + r * RS + c * 16) = w;
    }
    CP_WAIT0();
    __syncthreads();

    // ldmatrix base addresses
    uint32_t aA0 = sA + (wm * 32 + (lane & 15)) * RS + ((lane >> 4) << 4);
    uint32_t aA1 = aA0 + 16 * RS;
    uint32_t bBofs = (uint32_t)((wn * 32 + (lane & 7) + ((lane >> 4) << 3)) * RS
                                + (((lane >> 3) & 1) << 4));

    for (int ch = 0; ch < 4; ch++) {
        // prefetch next B chunk
        if (ch < 3) {
            const char* src = (const char*)g_eb + (size_t)(ch + 1) * 128 * 512;
            uint32_t dB = sB[(ch + 1) & 1];
            #pragma unroll
            for (int it = 0; it < 8; it++) {
                int t = tid + it * 512;
                int r = t >> 5, c = t & 31;
                CP_ASYNC16(dB + r * RS + c * 16, src + r * 512 + c * 16);
            }
            CP_COMMIT();
        }

        // ---- compute chunk ch: warp tile 32M x 32N ----
        float acc[2][4][4];
        #pragma unroll
        for (int i = 0; i < 2; i++)
            #pragma unroll
            for (int j = 0; j < 4; j++)
                #pragma unroll
                for (int q = 0; q < 4; q++) acc[i][j][q] = 0.0f;

        uint32_t bB = sB[ch & 1] + bBofs;
        #pragma unroll
        for (int ks = 0; ks < 16; ks++) {
            uint32_t ko = ks * 32;
            uint32_t a[2][4];
            LDSM4(a[0][0], a[0][1], a[0][2], a[0][3], aA0 + ko);
            LDSM4(a[1][0], a[1][1], a[1][2], a[1][3], aA1 + ko);
            #pragma unroll
            for (int p = 0; p < 2; p++) {
                uint32_t b0, b1, b2, b3;
                LDSM4(b0, b1, b2, b3, bB + p * (16 * RS) + ko);
                MMA16816(acc[0][2 * p],     a[0], b0, b1);
                MMA16816(acc[0][2 * p + 1], a[0], b2, b3);
                MMA16816(acc[1][2 * p],     a[1], b0, b1);
                MMA16816(acc[1][2 * p + 1], a[1], b2, b3);
            }
        }

        int cbase = ch * 128 + wn * 32 + (lane & 3) * 2;

        // ---- pass 1: per-row running max (transform acc -> v in place) ----
        #pragma unroll
        for (int im = 0; im < 2; im++) {
            #pragma unroll
            for (int h = 0; h < 2; h++) {
                float m = -3.0e38f;
                #pragma unroll
                for (int jn = 0; jn < 4; jn++) {
                    float v0 = fmaf(-2.0f, acc[im][jn][h * 2],     ceS[cbase + jn * 8]);
                    float v1 = fmaf(-2.0f, acc[im][jn][h * 2 + 1], ceS[cbase + jn * 8 + 1]);
                    acc[im][jn][h * 2] = v0;
                    acc[im][jn][h * 2 + 1] = v1;
                    m = fmaxf(m, fmaxf(v0, v1));
                }
                m = fmaxf(m, __shfl_xor_sync(0xffffffffu, m, 1));
                m = fmaxf(m, __shfl_xor_sync(0xffffffffu, m, 2));
                if ((lane & 3) == 0)
                    atomicMax(&rowBest[wm * 32 + im * 16 + h * 8 + (lane >> 2)], fmono(m));
            }
        }
        __syncthreads();

        // ---- pass 2: collect candidates v >= rowBest - MARGIN (superset-safe) ----
        #pragma unroll
        for (int im = 0; im < 2; im++) {
            #pragma unroll
            for (int h = 0; h < 2; h++) {
                int lrow = wm * 32 + im * 16 + h * 8 + (lane >> 2);
                float thr = funmono(rowBest[lrow]) - MARGIN;
                #pragma unroll
                for (int jn = 0; jn < 4; jn++) {
                    #pragma unroll
                    for (int q = 0; q < 2; q++) {
                        float v = acc[im][jn][h * 2 + q];
                        if (v >= thr) {
                            int pos = atomicAdd(&sCnt[lrow], 1);
                            if (pos < CAND) sCand[lrow * CAND + pos] = cbase + jn * 8 + q;
                        }
                    }
                }
            }
        }
        // rowBest only grows -> later (tighter) thresholds remain superset-safe

        if (ch < 3) {
            CP_WAIT0();
            __syncthreads();
        }
    }
    __syncthreads();

    // =============== fused epilogue: resolve + gather + loss + hist ===============
    float lossAcc = 0.0f;
    #pragma unroll 1
    for (int rr = 0; rr < 8; rr++) {
        int lrow = wid * 8 + rr;
        int row = rowBase + lrow;

        const float4* zp = (const float4*)(z + (size_t)row * DIMK);
        float4 a = zp[lane * 2], b = zp[lane * 2 + 1];

        int cnt = sCnt[lrow];
        int idx;
        if (cnt == 1) {
            idx = sCand[lrow * CAND];
        } else {
            float best = -3.0e38f;
            idx = NCODE;
            bool full = (cnt > CAND);
            int n = full ? NCODE : cnt;
            #pragma unroll 1
            for (int ci = 0; ci < n; ci++) {
                int c = full ? ci : sCand[lrow * CAND + ci];
                const float4* ep = (const float4*)(emb + (size_t)c * DIMK);
                float4 e0 = ep[lane * 2], e1 = ep[lane * 2 + 1];
                float s = a.x * e0.x + a.y * e0.y + a.z * e0.z + a.w * e0.w
                        + b.x * e1.x + b.y * e1.y + b.z * e1.z + b.w * e1.w;
                #pragma unroll
                for (int o = 16; o > 0; o >>= 1) s += __shfl_xor_sync(0xffffffffu, s, o);
                float sim = ceS[c] - 2.0f * s;
                if (sim > best || (sim == best && c < idx)) { best = sim; idx = c; }
            }
        }

        const float* er = emb + (size_t)idx * DIMK;
        float* oq = out + ZQ_OFF + (size_t)row * DIMK;
        float4 e0 = *(const float4*)(er + lane * 8);
        float4 e1 = *(const float4*)(er + lane * 8 + 4);
        *(float4*)(oq + lane * 8)     = e0;
        *(float4*)(oq + lane * 8 + 4) = e1;
        float d0 = e0.x - a.x, d1 = e0.y - a.y, d2 = e0.z - a.z, d3 = e0.w - a.w;
        float d4 = e1.x - b.x, d5 = e1.y - b.y, d6 = e1.z - b.z, d7 = e1.w - b.w;
        lossAcc += d0 * d0 + d1 * d1 + d2 * d2 + d3 * d3
                 + d4 * d4 + d5 * d5 + d6 * d6 + d7 * d7;

        if (lane == 0) {
            out[IDX_OFF + row] = (float)idx;
            atomicAdd(&out[HIST_OFF + idx], 1.0f);  // exact: integer-valued float adds
        }
    }

    // block-reduce loss partial (fixed order -> deterministic)
    #pragma unroll
    for (int o = 16; o > 0; o >>= 1) lossAcc += __shfl_down_sync(0xffffffffu, lossAcc, o);
    __shared__ float ws[16];
    __shared__ int lastFlag;
    if (lane == 0) ws[wid] = lossAcc;
    __syncthreads();
    if (tid == 0) {
        float t = 0.0f;
        #pragma unroll
        for (int i = 0; i < 16; i++) t += ws[i];
        g_part[blockIdx.x] = t;
        __threadfence();
        unsigned o = atomicAdd(&g_ctr, 1u);
        lastFlag = (o == NBLK - 1) ? 1 : 0;
    }
    __syncthreads();

    // ---- last CTA finalizes losses (fixed-order, deterministic) ----
    if (lastFlag) {
        float* ps = (float*)(smem + SM_CE);   // reuse ceS area: 512 floats
        float s = 0.0f;
        for (int i = tid; i < NBLK; i += 512) s += g_part[i];   // fixed order per thread
        ps[tid] = s;
        __syncthreads();
        if (tid == 0) {
            float tot = 0.0f;
            for (int i = 0; i < 512; i++) tot += ps[i];         // fixed order
            float vq = tot / 33554432.0f;   // N_ROWS * DIMK
            out[VQ_OFF] = vq;
            out[CM_OFF] = 0.25f * vq;
        }
    }
}

// no-op kernel: pads the launch sequence so ncu's capture lands on k_mma (4th launch)
__global__ void k_dummy() {}

// ---------------- Launch ----------------
extern "C" void kernel_launch(void* const* d_in, const int* in_sizes, int n_in,
                              void* d_out, int out_size) {
    const float* z   = (const float*)d_in[0];
    const float* emb = (const float*)d_in[1];
    float* out = (float*)d_out;

    cudaFuncSetAttribute(k_mma, cudaFuncAttributeMaxDynamicSharedMemorySize, SMEM_BYTES);

    k_prep<<<NCODE, 64>>>(emb, out);
    k_dummy<<<1, 32>>>();
    k_dummy<<<1, 32>>>();
    k_mma<<<NBLK, 512, SMEM_BYTES>>>(z, emb, out);
    k_dummy<<<1, 32>>>();
}

// round 14
// speedup vs baseline: 1.5494x; 1.5494x over previous
#include <cuda_runtime.h>
#include <cuda_bf16.h>
#include <cstdint>

// ---------------- Problem constants ----------------
#define N_ROWS   131072      // 32*16*16*16
#define DIMK     256         // E_DIM
#define NCODE    512         // N_EMBED

// Output layout (concatenated flattened outputs, float32):
#define ZQ_OFF   0
#define VQ_OFF   33554432
#define CM_OFF   33554433
#define IDX_OFF  33554434
#define HIST_OFF 33685506

#define NBLK (N_ROWS / 128)       // 1024 main blocks
#define MARGIN 0.8f               // ~6 sigma of bf16 sim-error difference (proven)
#define CAND   12                 // candidate slots per row

// ---------------- Device scratch (no allocations allowed) ----------------
__device__ __align__(16) __nv_bfloat16 g_eb[NCODE * DIMK];  // bf16 embedding
__device__ float g_ce[NCODE];             // ||e_n||^2 (fp32, exact)
__device__ float g_part[NBLK];            // loss partials

// ---------------- PTX helpers (portable to compute_103) ----------------
__device__ __forceinline__ uint32_t smem_u32(const void* p) {
    uint32_t a;
    asm("{ .reg .u64 t; cvta.to.shared.u64 t, %1; cvt.u32.u64 %0, t; }" : "=r"(a) : "l"(p));
    return a;
}
#define CP_ASYNC16(dst, src) \
    asm volatile("cp.async.cg.shared.global [%0], [%1], 16;" :: "r"(dst), "l"(src) : "memory")
#define CP_COMMIT() asm volatile("cp.async.commit_group;" ::: "memory")
#define CP_WAIT0()  asm volatile("cp.async.wait_group 0;" ::: "memory")
#define LDSM4(r0, r1, r2, r3, addr) \
    asm volatile("ldmatrix.sync.aligned.m8n8.x4.shared.b16 {%0,%1,%2,%3}, [%4];" \
        : "=r"(r0), "=r"(r1), "=r"(r2), "=r"(r3) : "r"(addr))
#define MMA16816(d, a, b0, b1) \
    asm volatile("mma.sync.aligned.m16n8k16.row.col.f32.bf16.bf16.f32 " \
        "{%0,%1,%2,%3},{%4,%5,%6,%7},{%8,%9},{%0,%1,%2,%3};" \
        : "+f"((d)[0]), "+f"((d)[1]), "+f"((d)[2]), "+f"((d)[3]) \
        : "r"((a)[0]), "r"((a)[1]), "r"((a)[2]), "r"((a)[3]), "r"(b0), "r"(b1))

// Monotone float<->uint map for atomicMax on floats
__device__ __forceinline__ unsigned fmono(float x) {
    unsigned u = __float_as_uint(x);
    return (u & 0x80000000u) ? ~u : (u | 0x80000000u);
}
__device__ __forceinline__ float funmono(unsigned u) {
    return (u & 0x80000000u) ? __uint_as_float(u ^ 0x80000000u) : __uint_as_float(~u);
}

// ---------------- SMEM layout (identical to R10) ----------------
#define RS 528                    // bf16 row pitch (264 bf16): conflict-reduced ldmatrix
#define SM_CE   0                 // 512 f32 = 2048B
#define SM_RB   2048              // 128 u32
#define SM_CNT  2560              // 128 s32
#define SM_CAND 3072              // 128 * 12 s32 = 6144
#define SM_A    9216              // 128 * 528 = 67584
#define SM_B0   76800             // 128 * 528
#define SM_B1   144384            // 128 * 528
#define SMEM_BYTES 211968

// ---------------- Kernel: prep (convert emb, norms, zero hist) ----------------
__global__ void k_prep(const float* __restrict__ emb, float* __restrict__ out) {
    int n = blockIdx.x;               // 512 blocks, 64 threads
    int t = threadIdx.x;
    float4 v = *(const float4*)(emb + (size_t)n * DIMK + t * 4);
    __nv_bfloat162 p0 = __floats2bfloat162_rn(v.x, v.y);
    __nv_bfloat162 p1 = __floats2bfloat162_rn(v.z, v.w);
    uint2 w;
    w.x = *(unsigned*)&p0;
    w.y = *(unsigned*)&p1;
    *(uint2*)((char*)g_eb + (size_t)n * 512 + t * 8) = w;
    float s = v.x * v.x + v.y * v.y + v.z * v.z + v.w * v.w;
    #pragma unroll
    for (int o = 16; o > 0; o >>= 1) s += __shfl_down_sync(0xffffffffu, s, o);
    __shared__ float ws[2];
    if ((t & 31) == 0) ws[t >> 5] = s;
    __syncthreads();
    if (t == 0) g_ce[n] = ws[0] + ws[1];
    if (n == 0) {
        #pragma unroll
        for (int k = 0; k < 8; k++) out[HIST_OFF + t + k * 64] = 0.0f;
    }
}

// ---------------- Kernel: HMMA GEMM (16 warps) + candidates + fused epilogue ----------------
__global__ __launch_bounds__(512, 1)
void k_mma(const float* __restrict__ z, const float* __restrict__ emb,
           float* __restrict__ out) {
    extern __shared__ __align__(128) unsigned char smem[];
    float*    ceS     = (float*)(smem + SM_CE);
    unsigned* rowBest = (unsigned*)(smem + SM_RB);
    int*      sCnt    = (int*)(smem + SM_CNT);
    int*      sCand   = (int*)(smem + SM_CAND);
    uint32_t sbase = smem_u32(smem);
    uint32_t sA  = sbase + SM_A;
    uint32_t sB[2] = { sbase + SM_B0, sbase + SM_B1 };

    int tid = threadIdx.x, lane = tid & 31, wid = tid >> 5;
    int wm = wid & 3;        // M block: 32 rows
    int wn = wid >> 2;       // N block: 32 cols (4 groups cover 128-col chunk)
    int rowBase = blockIdx.x * 128;

    if (tid < NCODE) ceS[tid] = g_ce[tid];
    if (tid < 128) { rowBest[tid] = 0u; sCnt[tid] = 0; }

    // ---- prefetch B chunk 0 (128 rows x 32 16B-units) ----
    {
        const char* src = (const char*)g_eb;
        #pragma unroll
        for (int it = 0; it < 8; it++) {
            int t = tid + it * 512;
            int r = t >> 5, c = t & 31;
            CP_ASYNC16(sB[0] + r * RS + c * 16, src + r * 512 + c * 16);
        }
        CP_COMMIT();
    }

    // ---- load + convert A tile: 128 rows x 256 fp32 -> bf16, padded rows ----
    #pragma unroll
    for (int it = 0; it < 8; it++) {
        int t = tid + it * 512;
        int r = t >> 5, c = t & 31;
        const float4* zp = (const float4*)(z + (size_t)(rowBase + r) * DIMK + c * 8);
        float4 u0 = zp[0], u1 = zp[1];
        __nv_bfloat162 p0 = __floats2bfloat162_rn(u0.x, u0.y);
        __nv_bfloat162 p1 = __floats2bfloat162_rn(u0.z, u0.w);
        __nv_bfloat162 p2 = __floats2bfloat162_rn(u1.x, u1.y);
        __nv_bfloat162 p3 = __floats2bfloat162_rn(u1.z, u1.w);
        uint4 w;
        w.x = *(unsigned*)&p0; w.y = *(unsigned*)&p1;
        w.z = *(unsigned*)&p2; w.w = *(unsigned*)&p3;
        *(uint4*)(smem + SM_A + r * RS + c * 16) = w;
    }
    CP_WAIT0();
    __syncthreads();

    // ldmatrix base addresses
    uint32_t aA0 = sA + (wm * 32 + (lane & 15)) * RS + ((lane >> 4) << 4);
    uint32_t aA1 = aA0 + 16 * RS;
    uint32_t bBofs = (uint32_t)((wn * 32 + (lane & 7) + ((lane >> 4) << 3)) * RS
                                + (((lane >> 3) & 1) << 4));

    for (int ch = 0; ch < 4; ch++) {
        // prefetch next B chunk
        if (ch < 3) {
            const char* src = (const char*)g_eb + (size_t)(ch + 1) * 128 * 512;
            uint32_t dB = sB[(ch + 1) & 1];
            #pragma unroll
            for (int it = 0; it < 8; it++) {
                int t = tid + it * 512;
                int r = t >> 5, c = t & 31;
                CP_ASYNC16(dB + r * RS + c * 16, src + r * 512 + c * 16);
            }
            CP_COMMIT();
        }

        // ---- compute chunk ch: warp tile 32M x 32N ----
        float acc[2][4][4];
        #pragma unroll
        for (int i = 0; i < 2; i++)
            #pragma unroll
            for (int j = 0; j < 4; j++)
                #pragma unroll
                for (int q = 0; q < 4; q++) acc[i][j][q] = 0.0f;

        uint32_t bB = sB[ch & 1] + bBofs;
        #pragma unroll
        for (int ks = 0; ks < 16; ks++) {
            uint32_t ko = ks * 32;
            uint32_t a[2][4];
            LDSM4(a[0][0], a[0][1], a[0][2], a[0][3], aA0 + ko);
            LDSM4(a[1][0], a[1][1], a[1][2], a[1][3], aA1 + ko);
            #pragma unroll
            for (int p = 0; p < 2; p++) {
                uint32_t b0, b1, b2, b3;
                LDSM4(b0, b1, b2, b3, bB + p * (16 * RS) + ko);
                MMA16816(acc[0][2 * p],     a[0], b0, b1);
                MMA16816(acc[0][2 * p + 1], a[0], b2, b3);
                MMA16816(acc[1][2 * p],     a[1], b0, b1);
                MMA16816(acc[1][2 * p + 1], a[1], b2, b3);
            }
        }

        int cbase = ch * 128 + wn * 32 + (lane & 3) * 2;

        // ---- pass 1: per-row running max (transform acc -> v in place) ----
        #pragma unroll
        for (int im = 0; im < 2; im++) {
            #pragma unroll
            for (int h = 0; h < 2; h++) {
                float m = -3.0e38f;
                #pragma unroll
                for (int jn = 0; jn < 4; jn++) {
                    float v0 = fmaf(-2.0f, acc[im][jn][h * 2],     ceS[cbase + jn * 8]);
                    float v1 = fmaf(-2.0f, acc[im][jn][h * 2 + 1], ceS[cbase + jn * 8 + 1]);
                    acc[im][jn][h * 2] = v0;
                    acc[im][jn][h * 2 + 1] = v1;
                    m = fmaxf(m, fmaxf(v0, v1));
                }
                m = fmaxf(m, __shfl_xor_sync(0xffffffffu, m, 1));
                m = fmaxf(m, __shfl_xor_sync(0xffffffffu, m, 2));
                if ((lane & 3) == 0)
                    atomicMax(&rowBest[wm * 32 + im * 16 + h * 8 + (lane >> 2)], fmono(m));
            }
        }
        __syncthreads();

        // ---- pass 2: collect candidates v >= rowBest - MARGIN (superset-safe) ----
        #pragma unroll
        for (int im = 0; im < 2; im++) {
            #pragma unroll
            for (int h = 0; h < 2; h++) {
                int lrow = wm * 32 + im * 16 + h * 8 + (lane >> 2);
                float thr = funmono(rowBest[lrow]) - MARGIN;
                #pragma unroll
                for (int jn = 0; jn < 4; jn++) {
                    #pragma unroll
                    for (int q = 0; q < 2; q++) {
                        float v = acc[im][jn][h * 2 + q];
                        if (v >= thr) {
                            int pos = atomicAdd(&sCnt[lrow], 1);
                            if (pos < CAND) sCand[lrow * CAND + pos] = cbase + jn * 8 + q;
                        }
                    }
                }
            }
        }
        // rowBest only grows -> later (tighter) thresholds remain superset-safe

        if (ch < 3) {
            CP_WAIT0();
            __syncthreads();
        }
    }
    __syncthreads();

    // =============== fused epilogue: resolve + gather + loss + hist ===============
    float lossAcc = 0.0f;
    #pragma unroll 1
    for (int rr = 0; rr < 8; rr++) {
        int lrow = wid * 8 + rr;
        int row = rowBase + lrow;

        const float4* zp = (const float4*)(z + (size_t)row * DIMK);
        float4 a = zp[lane * 2], b = zp[lane * 2 + 1];

        int cnt = sCnt[lrow];
        int idx;
        if (cnt == 1) {
            idx = sCand[lrow * CAND];
        } else {
            float best = -3.0e38f;
            idx = NCODE;
            bool full = (cnt > CAND);
            int n = full ? NCODE : cnt;
            #pragma unroll 1
            for (int ci = 0; ci < n; ci++) {
                int c = full ? ci : sCand[lrow * CAND + ci];
                const float4* ep = (const float4*)(emb + (size_t)c * DIMK);
                float4 e0 = ep[lane * 2], e1 = ep[lane * 2 + 1];
                float s = a.x * e0.x + a.y * e0.y + a.z * e0.z + a.w * e0.w
                        + b.x * e1.x + b.y * e1.y + b.z * e1.z + b.w * e1.w;
                #pragma unroll
                for (int o = 16; o > 0; o >>= 1) s += __shfl_xor_sync(0xffffffffu, s, o);
                float sim = ceS[c] - 2.0f * s;
                if (sim > best || (sim == best && c < idx)) { best = sim; idx = c; }
            }
        }

        const float* er = emb + (size_t)idx * DIMK;
        float* oq = out + ZQ_OFF + (size_t)row * DIMK;
        float4 e0 = *(const float4*)(er + lane * 8);
        float4 e1 = *(const float4*)(er + lane * 8 + 4);
        *(float4*)(oq + lane * 8)     = e0;
        *(float4*)(oq + lane * 8 + 4) = e1;
        float d0 = e0.x - a.x, d1 = e0.y - a.y, d2 = e0.z - a.z, d3 = e0.w - a.w;
        float d4 = e1.x - b.x, d5 = e1.y - b.y, d6 = e1.z - b.z, d7 = e1.w - b.w;
        lossAcc += d0 * d0 + d1 * d1 + d2 * d2 + d3 * d3
                 + d4 * d4 + d5 * d5 + d6 * d6 + d7 * d7;

        if (lane == 0) {
            out[IDX_OFF + row] = (float)idx;
            atomicAdd(&out[HIST_OFF + idx], 1.0f);  // exact: integer-valued float adds
        }
    }

    // block-reduce loss partial (fixed order -> deterministic)
    #pragma unroll
    for (int o = 16; o > 0; o >>= 1) lossAcc += __shfl_down_sync(0xffffffffu, lossAcc, o);
    __shared__ float ws[16];
    if (lane == 0) ws[wid] = lossAcc;
    __syncthreads();
    if (tid == 0) {
        float t = 0.0f;
        #pragma unroll
        for (int i = 0; i < 16; i++) t += ws[i];
        g_part[blockIdx.x] = t;
    }
}

// ---------------- Kernel: finalize losses (fixed-pairing tree, deterministic) ----------------
__global__ __launch_bounds__(1024) void k_final(float* __restrict__ out) {
    __shared__ float ps[1024];
    int t = threadIdx.x;
    ps[t] = g_part[t];                 // NBLK == 1024, one partial per thread
    __syncthreads();
    #pragma unroll
    for (int s = 512; s > 0; s >>= 1) {   // fixed pairing every replay -> deterministic
        if (t < s) ps[t] += ps[t + s];
        __syncthreads();
    }
    if (t == 0) {
        float vq = ps[0] / 33554432.0f;   // N_ROWS * DIMK
        out[VQ_OFF] = vq;
        out[CM_OFF] = 0.25f * vq;
    }
}

// no-op kernel: pads the launch sequence so ncu's capture (4th launch) lands on k_mma
__global__ void k_dummy() {}

// ---------------- Launch ----------------
extern "C" void kernel_launch(void* const* d_in, const int* in_sizes, int n_in,
                              void* d_out, int out_size) {
    const float* z   = (const float*)d_in[0];
    const float* emb = (const float*)d_in[1];
    float* out = (float*)d_out;

    cudaFuncSetAttribute(k_mma, cudaFuncAttributeMaxDynamicSharedMemorySize, SMEM_BYTES);

    k_prep<<<NCODE, 64>>>(emb, out);
    k_dummy<<<1, 32>>>();
    k_dummy<<<1, 32>>>();
    k_mma<<<NBLK, 512, SMEM_BYTES>>>(z, emb, out);
    k_final<<<1, 1024>>>(out);
}

// round 15
// speedup vs baseline: 1.5652x; 1.0102x over previous
#include <cuda_runtime.h>
#include <cuda_bf16.h>
#include <cstdint>

// ---------------- Problem constants ----------------
#define N_ROWS   131072      // 32*16*16*16
#define DIMK     256         // E_DIM
#define NCODE    512         // N_EMBED

// Output layout (concatenated flattened outputs, float32):
#define ZQ_OFF   0
#define VQ_OFF   33554432
#define CM_OFF   33554433
#define IDX_OFF  33554434
#define HIST_OFF 33685506

#define NBLK (N_ROWS / 128)       // 1024 main blocks
#define MARGIN 0.8f               // ~6 sigma of bf16 sim-error difference (proven)
#define CAND   12                 // candidate slots per row

// ---------------- Device scratch (no allocations allowed) ----------------
__device__ __align__(16) __nv_bfloat16 g_eb[NCODE * DIMK];  // bf16 embedding
__device__ float g_ce[NCODE];             // ||e_n||^2 (fp32, exact)
__device__ float g_part[NBLK];            // loss partials

// ---------------- PTX helpers (portable to compute_103) ----------------
__device__ __forceinline__ uint32_t smem_u32(const void* p) {
    uint32_t a;
    asm("{ .reg .u64 t; cvta.to.shared.u64 t, %1; cvt.u32.u64 %0, t; }" : "=r"(a) : "l"(p));
    return a;
}
#define CP_ASYNC16(dst, src) \
    asm volatile("cp.async.cg.shared.global [%0], [%1], 16;" :: "r"(dst), "l"(src) : "memory")
#define CP_COMMIT() asm volatile("cp.async.commit_group;" ::: "memory")
#define CP_WAIT0()  asm volatile("cp.async.wait_group 0;" ::: "memory")
#define LDSM4(r0, r1, r2, r3, addr) \
    asm volatile("ldmatrix.sync.aligned.m8n8.x4.shared.b16 {%0,%1,%2,%3}, [%4];" \
        : "=r"(r0), "=r"(r1), "=r"(r2), "=r"(r3) : "r"(addr))
#define MMA16816(d, a, b0, b1) \
    asm volatile("mma.sync.aligned.m16n8k16.row.col.f32.bf16.bf16.f32 " \
        "{%0,%1,%2,%3},{%4,%5,%6,%7},{%8,%9},{%0,%1,%2,%3};" \
        : "+f"((d)[0]), "+f"((d)[1]), "+f"((d)[2]), "+f"((d)[3]) \
        : "r"((a)[0]), "r"((a)[1]), "r"((a)[2]), "r"((a)[3]), "r"(b0), "r"(b1))

// Monotone float<->uint map for atomicMax on floats
__device__ __forceinline__ unsigned fmono(float x) {
    unsigned u = __float_as_uint(x);
    return (u & 0x80000000u) ? ~u : (u | 0x80000000u);
}
__device__ __forceinline__ float funmono(unsigned u) {
    return (u & 0x80000000u) ? __uint_as_float(u ^ 0x80000000u) : __uint_as_float(~u);
}

// ---------------- SMEM layout (identical to R10/R14) ----------------
#define RS 528                    // bf16 row pitch (264 bf16): conflict-reduced ldmatrix
#define SM_CE   0                 // 512 f32 = 2048B
#define SM_RB   2048              // 128 u32
#define SM_CNT  2560              // 128 s32
#define SM_CAND 3072              // 128 * 12 s32 = 6144
#define SM_A    9216              // 128 * 528 = 67584
#define SM_B0   76800             // 128 * 528
#define SM_B1   144384            // 128 * 528
#define SMEM_BYTES 211968

// ---------------- Kernel: prep (convert emb, norms, zero hist) ----------------
__global__ void k_prep(const float* __restrict__ emb, float* __restrict__ out) {
    int n = blockIdx.x;               // 512 blocks, 64 threads
    int t = threadIdx.x;
    float4 v = *(const float4*)(emb + (size_t)n * DIMK + t * 4);
    __nv_bfloat162 p0 = __floats2bfloat162_rn(v.x, v.y);
    __nv_bfloat162 p1 = __floats2bfloat162_rn(v.z, v.w);
    uint2 w;
    w.x = *(unsigned*)&p0;
    w.y = *(unsigned*)&p1;
    *(uint2*)((char*)g_eb + (size_t)n * 512 + t * 8) = w;
    float s = v.x * v.x + v.y * v.y + v.z * v.z + v.w * v.w;
    #pragma unroll
    for (int o = 16; o > 0; o >>= 1) s += __shfl_down_sync(0xffffffffu, s, o);
    __shared__ float ws[2];
    if ((t & 31) == 0) ws[t >> 5] = s;
    __syncthreads();
    if (t == 0) g_ce[n] = ws[0] + ws[1];
    if (n == 0) {
        #pragma unroll
        for (int k = 0; k < 8; k++) out[HIST_OFF + t + k * 64] = 0.0f;
    }
}

// ---------------- Kernel: HMMA GEMM (16 warps) + candidates + fused epilogue ----------------
__global__ __launch_bounds__(512, 1)
void k_mma(const float* __restrict__ z, const float* __restrict__ emb,
           float* __restrict__ out) {
    extern __shared__ __align__(128) unsigned char smem[];
    float*    ceS     = (float*)(smem + SM_CE);
    unsigned* rowBest = (unsigned*)(smem + SM_RB);
    int*      sCnt    = (int*)(smem + SM_CNT);
    int*      sCand   = (int*)(smem + SM_CAND);
    uint32_t sbase = smem_u32(smem);
    uint32_t sA  = sbase + SM_A;
    uint32_t sB[2] = { sbase + SM_B0, sbase + SM_B1 };

    int tid = threadIdx.x, lane = tid & 31, wid = tid >> 5;
    int wm = wid & 3;        // M block: 32 rows
    int wn = wid >> 2;       // N block: 32 cols (4 groups cover 128-col chunk)
    int rowBase = blockIdx.x * 128;

    if (tid < NCODE) ceS[tid] = g_ce[tid];
    if (tid < 128) { rowBest[tid] = 0u; sCnt[tid] = 0; }

    // ---- prefetch B chunk 0 (128 rows x 32 16B-units) ----
    {
        const char* src = (const char*)g_eb;
        #pragma unroll
        for (int it = 0; it < 8; it++) {
            int t = tid + it * 512;
            int r = t >> 5, c = t & 31;
            CP_ASYNC16(sB[0] + r * RS + c * 16, src + r * 512 + c * 16);
        }
        CP_COMMIT();
    }

    // ---- load + convert A tile: 128 rows x 256 fp32 -> bf16, padded rows ----
    #pragma unroll
    for (int it = 0; it < 8; it++) {
        int t = tid + it * 512;
        int r = t >> 5, c = t & 31;
        const float4* zp = (const float4*)(z + (size_t)(rowBase + r) * DIMK + c * 8);
        float4 u0 = zp[0], u1 = zp[1];
        __nv_bfloat162 p0 = __floats2bfloat162_rn(u0.x, u0.y);
        __nv_bfloat162 p1 = __floats2bfloat162_rn(u0.z, u0.w);
        __nv_bfloat162 p2 = __floats2bfloat162_rn(u1.x, u1.y);
        __nv_bfloat162 p3 = __floats2bfloat162_rn(u1.z, u1.w);
        uint4 w;
        w.x = *(unsigned*)&p0; w.y = *(unsigned*)&p1;
        w.z = *(unsigned*)&p2; w.w = *(unsigned*)&p3;
        *(uint4*)(smem + SM_A + r * RS + c * 16) = w;
    }
    CP_WAIT0();
    __syncthreads();

    // ldmatrix base addresses
    uint32_t aA0 = sA + (wm * 32 + (lane & 15)) * RS + ((lane >> 4) << 4);
    uint32_t aA1 = aA0 + 16 * RS;
    uint32_t bBofs = (uint32_t)((wn * 32 + (lane & 7) + ((lane >> 4) << 3)) * RS
                                + (((lane >> 3) & 1) << 4));

    for (int ch = 0; ch < 4; ch++) {
        // prefetch next B chunk
        if (ch < 3) {
            const char* src = (const char*)g_eb + (size_t)(ch + 1) * 128 * 512;
            uint32_t dB = sB[(ch + 1) & 1];
            #pragma unroll
            for (int it = 0; it < 8; it++) {
                int t = tid + it * 512;
                int r = t >> 5, c = t & 31;
                CP_ASYNC16(dB + r * RS + c * 16, src + r * 512 + c * 16);
            }
            CP_COMMIT();
        }

        // ---- compute chunk ch: warp tile 32M x 32N ----
        float acc[2][4][4];
        #pragma unroll
        for (int i = 0; i < 2; i++)
            #pragma unroll
            for (int j = 0; j < 4; j++)
                #pragma unroll
                for (int q = 0; q < 4; q++) acc[i][j][q] = 0.0f;

        uint32_t bB = sB[ch & 1] + bBofs;
        #pragma unroll
        for (int ks = 0; ks < 16; ks++) {
            uint32_t ko = ks * 32;
            uint32_t a[2][4];
            LDSM4(a[0][0], a[0][1], a[0][2], a[0][3], aA0 + ko);
            LDSM4(a[1][0], a[1][1], a[1][2], a[1][3], aA1 + ko);
            #pragma unroll
            for (int p = 0; p < 2; p++) {
                uint32_t b0, b1, b2, b3;
                LDSM4(b0, b1, b2, b3, bB + p * (16 * RS) + ko);
                MMA16816(acc[0][2 * p],     a[0], b0, b1);
                MMA16816(acc[0][2 * p + 1], a[0], b2, b3);
                MMA16816(acc[1][2 * p],     a[1], b0, b1);
                MMA16816(acc[1][2 * p + 1], a[1], b2, b3);
            }
        }

        int cbase = ch * 128 + wn * 32 + (lane & 3) * 2;

        // ---- pass 1: per-row running max (transform acc -> v in place) ----
        #pragma unroll
        for (int im = 0; im < 2; im++) {
            #pragma unroll
            for (int h = 0; h < 2; h++) {
                float m = -3.0e38f;
                #pragma unroll
                for (int jn = 0; jn < 4; jn++) {
                    float v0 = fmaf(-2.0f, acc[im][jn][h * 2],     ceS[cbase + jn * 8]);
                    float v1 = fmaf(-2.0f, acc[im][jn][h * 2 + 1], ceS[cbase + jn * 8 + 1]);
                    acc[im][jn][h * 2] = v0;
                    acc[im][jn][h * 2 + 1] = v1;
                    m = fmaxf(m, fmaxf(v0, v1));
                }
                m = fmaxf(m, __shfl_xor_sync(0xffffffffu, m, 1));
                m = fmaxf(m, __shfl_xor_sync(0xffffffffu, m, 2));
                if ((lane & 3) == 0)
                    atomicMax(&rowBest[wm * 32 + im * 16 + h * 8 + (lane >> 2)], fmono(m));
            }
        }
        __syncthreads();

        // ---- pass 2: collect candidates v >= rowBest - MARGIN (superset-safe) ----
        #pragma unroll
        for (int im = 0; im < 2; im++) {
            #pragma unroll
            for (int h = 0; h < 2; h++) {
                int lrow = wm * 32 + im * 16 + h * 8 + (lane >> 2);
                float thr = funmono(rowBest[lrow]) - MARGIN;
                #pragma unroll
                for (int jn = 0; jn < 4; jn++) {
                    #pragma unroll
                    for (int q = 0; q < 2; q++) {
                        float v = acc[im][jn][h * 2 + q];
                        if (v >= thr) {
                            int pos = atomicAdd(&sCnt[lrow], 1);
                            if (pos < CAND) sCand[lrow * CAND + pos] = cbase + jn * 8 + q;
                        }
                    }
                }
            }
        }
        // rowBest only grows -> later (tighter) thresholds remain superset-safe

        if (ch < 3) {
            CP_WAIT0();
            __syncthreads();
        }
    }
    __syncthreads();

    // =============== fused epilogue: resolve + gather + loss + hist ===============
    float lossAcc = 0.0f;
    #pragma unroll 1
    for (int rr = 0; rr < 8; rr++) {
        int lrow = wid * 8 + rr;
        int row = rowBase + lrow;

        const float4* zp = (const float4*)(z + (size_t)row * DIMK);
        float4 a = zp[lane * 2], b = zp[lane * 2 + 1];

        int cnt = sCnt[lrow];
        int idx;
        if (cnt == 1) {
            idx = sCand[lrow * CAND];
        } else {
            float best = -3.0e38f;
            idx = NCODE;
            bool full = (cnt > CAND);
            int n = full ? NCODE : cnt;
            #pragma unroll 1
            for (int ci = 0; ci < n; ci++) {
                int c = full ? ci : sCand[lrow * CAND + ci];
                const float4* ep = (const float4*)(emb + (size_t)c * DIMK);
                float4 e0 = ep[lane * 2], e1 = ep[lane * 2 + 1];
                float s = a.x * e0.x + a.y * e0.y + a.z * e0.z + a.w * e0.w
                        + b.x * e1.x + b.y * e1.y + b.z * e1.z + b.w * e1.w;
                #pragma unroll
                for (int o = 16; o > 0; o >>= 1) s += __shfl_xor_sync(0xffffffffu, s, o);
                float sim = ceS[c] - 2.0f * s;
                if (sim > best || (sim == best && c < idx)) { best = sim; idx = c; }
            }
        }

        const float* er = emb + (size_t)idx * DIMK;
        float* oq = out + ZQ_OFF + (size_t)row * DIMK;
        float4 e0 = *(const float4*)(er + lane * 8);
        float4 e1 = *(const float4*)(er + lane * 8 + 4);
        *(float4*)(oq + lane * 8)     = e0;
        *(float4*)(oq + lane * 8 + 4) = e1;
        float d0 = e0.x - a.x, d1 = e0.y - a.y, d2 = e0.z - a.z, d3 = e0.w - a.w;
        float d4 = e1.x - b.x, d5 = e1.y - b.y, d6 = e1.z - b.z, d7 = e1.w - b.w;
        lossAcc += d0 * d0 + d1 * d1 + d2 * d2 + d3 * d3
                 + d4 * d4 + d5 * d5 + d6 * d6 + d7 * d7;

        if (lane == 0) {
            out[IDX_OFF + row] = (float)idx;
            atomicAdd(&out[HIST_OFF + idx], 1.0f);  // exact: integer-valued float adds
        }
    }

    // block-reduce loss partial (fixed order -> deterministic)
    #pragma unroll
    for (int o = 16; o > 0; o >>= 1) lossAcc += __shfl_down_sync(0xffffffffu, lossAcc, o);
    __shared__ float ws[16];
    if (lane == 0) ws[wid] = lossAcc;
    __syncthreads();
    if (tid == 0) {
        float t = 0.0f;
        #pragma unroll
        for (int i = 0; i < 16; i++) t += ws[i];
        g_part[blockIdx.x] = t;
    }
}

// ---------------- Kernel: finalize losses (fixed-pairing tree, deterministic) ----------------
__global__ __launch_bounds__(1024) void k_final(float* __restrict__ out) {
    __shared__ float ps[1024];
    int t = threadIdx.x;
    ps[t] = g_part[t];                 // NBLK == 1024, one partial per thread
    __syncthreads();
    #pragma unroll
    for (int s = 512; s > 0; s >>= 1) {   // fixed pairing every replay -> deterministic
        if (t < s) ps[t] += ps[t + s];
        __syncthreads();
    }
    if (t == 0) {
        float vq = ps[0] / 33554432.0f;   // N_ROWS * DIMK
        out[VQ_OFF] = vq;
        out[CM_OFF] = 0.25f * vq;
    }
}

// ---------------- Launch ----------------
extern "C" void kernel_launch(void* const* d_in, const int* in_sizes, int n_in,
                              void* d_out, int out_size) {
    const float* z   = (const float*)d_in[0];
    const float* emb = (const float*)d_in[1];
    float* out = (float*)d_out;

    cudaFuncSetAttribute(k_mma, cudaFuncAttributeMaxDynamicSharedMemorySize, SMEM_BYTES);

    k_prep<<<NCODE, 64>>>(emb, out);
    k_mma<<<NBLK, 512, SMEM_BYTES>>>(z, emb, out);
    k_final<<<1, 1024>>>(out);
}

// round 17
// speedup vs baseline: 1.5798x; 1.0093x over previous
#include <cuda_runtime.h>
#include <cuda_bf16.h>
#include <cstdint>

// ---------------- Problem constants ----------------
#define N_ROWS   131072      // 32*16*16*16
#define DIMK     256         // E_DIM
#define NCODE    512         // N_EMBED

// Output layout (concatenated flattened outputs, float32):
#define ZQ_OFF   0
#define VQ_OFF   33554432
#define CM_OFF   33554433
#define IDX_OFF  33554434
#define HIST_OFF 33685506

#define NBLK (N_ROWS / 128)       // 1024 main blocks
#define MARGIN 0.8f               // ~6 sigma of bf16 sim-error difference (proven)
#define CAND   12                 // candidate slots per row

// ---------------- Device scratch (no allocations allowed) ----------------
__device__ __align__(16) __nv_bfloat16 g_eb[NCODE * DIMK];  // bf16 embedding
__device__ float g_ce[NCODE];             // ||e_n||^2 (fp32, exact)
__device__ float g_part[NBLK];            // loss partials

// ---------------- PTX helpers (portable to compute_103) ----------------
__device__ __forceinline__ uint32_t smem_u32(const void* p) {
    uint32_t a;
    asm("{ .reg .u64 t; cvta.to.shared.u64 t, %1; cvt.u32.u64 %0, t; }" : "=r"(a) : "l"(p));
    return a;
}
#define CP_ASYNC16(dst, src) \
    asm volatile("cp.async.cg.shared.global [%0], [%1], 16;" :: "r"(dst), "l"(src) : "memory")
#define CP_COMMIT() asm volatile("cp.async.commit_group;" ::: "memory")
#define CP_WAIT0()  asm volatile("cp.async.wait_group 0;" ::: "memory")
#define LDSM4(r0, r1, r2, r3, addr) \
    asm volatile("ldmatrix.sync.aligned.m8n8.x4.shared.b16 {%0,%1,%2,%3}, [%4];" \
        : "=r"(r0), "=r"(r1), "=r"(r2), "=r"(r3) : "r"(addr))
#define MMA16816(d, a, b0, b1) \
    asm volatile("mma.sync.aligned.m16n8k16.row.col.f32.bf16.bf16.f32 " \
        "{%0,%1,%2,%3},{%4,%5,%6,%7},{%8,%9},{%0,%1,%2,%3};" \
        : "+f"((d)[0]), "+f"((d)[1]), "+f"((d)[2]), "+f"((d)[3]) \
        : "r"((a)[0]), "r"((a)[1]), "r"((a)[2]), "r"((a)[3]), "r"(b0), "r"(b1))

// Monotone float<->uint map for atomicMax on floats
__device__ __forceinline__ unsigned fmono(float x) {
    unsigned u = __float_as_uint(x);
    return (u & 0x80000000u) ? ~u : (u | 0x80000000u);
}
__device__ __forceinline__ float funmono(unsigned u) {
    return (u & 0x80000000u) ? __uint_as_float(u ^ 0x80000000u) : __uint_as_float(~u);
}

// ---------------- SMEM layout (identical to R10/R14/R15) ----------------
#define RS 528                    // bf16 row pitch (264 bf16): conflict-reduced ldmatrix
#define SM_CE   0                 // 512 f32 = 2048B
#define SM_RB   2048              // 128 u32
#define SM_CNT  2560              // 128 s32
#define SM_CAND 3072              // 128 * 12 s32 = 6144
#define SM_A    9216              // 128 * 528 = 67584
#define SM_B0   76800             // 128 * 528
#define SM_B1   144384            // 128 * 528
#define SMEM_BYTES 211968

// ---------------- Kernel: prep (convert emb, norms, zero hist) ----------------
__global__ void k_prep(const float* __restrict__ emb, float* __restrict__ out) {
    int n = blockIdx.x;               // 512 blocks, 64 threads
    int t = threadIdx.x;
    float4 v = *(const float4*)(emb + (size_t)n * DIMK + t * 4);
    __nv_bfloat162 p0 = __floats2bfloat162_rn(v.x, v.y);
    __nv_bfloat162 p1 = __floats2bfloat162_rn(v.z, v.w);
    uint2 w;
    w.x = *(unsigned*)&p0;
    w.y = *(unsigned*)&p1;
    *(uint2*)((char*)g_eb + (size_t)n * 512 + t * 8) = w;
    float s = v.x * v.x + v.y * v.y + v.z * v.z + v.w * v.w;
    #pragma unroll
    for (int o = 16; o > 0; o >>= 1) s += __shfl_down_sync(0xffffffffu, s, o);
    __shared__ float ws[2];
    if ((t & 31) == 0) ws[t >> 5] = s;
    __syncthreads();
    if (t == 0) g_ce[n] = ws[0] + ws[1];
    if (n == 0) {
        #pragma unroll
        for (int k = 0; k < 8; k++) out[HIST_OFF + t + k * 64] = 0.0f;
    }
    // all global writes for this block are done -> allow dependent k_mma to start
    cudaTriggerProgrammaticLaunchCompletion();
}

// ---------------- Kernel: HMMA GEMM (16 warps) + candidates + fused epilogue ----------------
__global__ __launch_bounds__(512, 1)
void k_mma(const float* __restrict__ z, const float* __restrict__ emb,
           float* __restrict__ out) {
    extern __shared__ __align__(128) unsigned char smem[];
    float*    ceS     = (float*)(smem + SM_CE);
    unsigned* rowBest = (unsigned*)(smem + SM_RB);
    int*      sCnt    = (int*)(smem + SM_CNT);
    int*      sCand   = (int*)(smem + SM_CAND);
    uint32_t sbase = smem_u32(smem);
    uint32_t sA  = sbase + SM_A;
    uint32_t sB[2] = { sbase + SM_B0, sbase + SM_B1 };

    int tid = threadIdx.x, lane = tid & 31, wid = tid >> 5;
    int wm = wid & 3;        // M block: 32 rows
    int wn = wid >> 2;       // N block: 32 cols (4 groups cover 128-col chunk)
    int rowBase = blockIdx.x * 128;

    if (tid < 128) { rowBest[tid] = 0u; sCnt[tid] = 0; }

    // ---- load + convert A tile FIRST (reads only z -> overlaps k_prep via PDL) ----
    #pragma unroll
    for (int it = 0; it < 8; it++) {
        int t = tid + it * 512;
        int r = t >> 5, c = t & 31;
        const float4* zp = (const float4*)(z + (size_t)(rowBase + r) * DIMK + c * 8);
        float4 u0 = zp[0], u1 = zp[1];
        __nv_bfloat162 p0 = __floats2bfloat162_rn(u0.x, u0.y);
        __nv_bfloat162 p1 = __floats2bfloat162_rn(u0.z, u0.w);
        __nv_bfloat162 p2 = __floats2bfloat162_rn(u1.x, u1.y);
        __nv_bfloat162 p3 = __floats2bfloat162_rn(u1.z, u1.w);
        uint4 w;
        w.x = *(unsigned*)&p0; w.y = *(unsigned*)&p1;
        w.z = *(unsigned*)&p2; w.w = *(unsigned*)&p3;
        *(uint4*)(smem + SM_A + r * RS + c * 16) = w;
    }

    // ---- wait for k_prep's writes (g_eb, g_ce) to be visible ----
    cudaGridDependencySynchronize();

    if (tid < NCODE) ceS[tid] = g_ce[tid];

    // ---- prefetch B chunk 0 (128 rows x 32 16B-units) ----
    {
        const char* src = (const char*)g_eb;
        #pragma unroll
        for (int it = 0; it < 8; it++) {
            int t = tid + it * 512;
            int r = t >> 5, c = t & 31;
            CP_ASYNC16(sB[0] + r * RS + c * 16, src + r * 512 + c * 16);
        }
        CP_COMMIT();
    }
    CP_WAIT0();
    __syncthreads();

    // ldmatrix base addresses
    uint32_t aA0 = sA + (wm * 32 + (lane & 15)) * RS + ((lane >> 4) << 4);
    uint32_t aA1 = aA0 + 16 * RS;
    uint32_t bBofs = (uint32_t)((wn * 32 + (lane & 7) + ((lane >> 4) << 3)) * RS
                                + (((lane >> 3) & 1) << 4));

    for (int ch = 0; ch < 4; ch++) {
        // prefetch next B chunk
        if (ch < 3) {
            const char* src = (const char*)g_eb + (size_t)(ch + 1) * 128 * 512;
            uint32_t dB = sB[(ch + 1) & 1];
            #pragma unroll
            for (int it = 0; it < 8; it++) {
                int t = tid + it * 512;
                int r = t >> 5, c = t & 31;
                CP_ASYNC16(dB + r * RS + c * 16, src + r * 512 + c * 16);
            }
            CP_COMMIT();
        }

        // ---- compute chunk ch: warp tile 32M x 32N ----
        float acc[2][4][4];
        #pragma unroll
        for (int i = 0; i < 2; i++)
            #pragma unroll
            for (int j = 0; j < 4; j++)
                #pragma unroll
                for (int q = 0; q < 4; q++) acc[i][j][q] = 0.0f;

        uint32_t bB = sB[ch & 1] + bBofs;
        #pragma unroll
        for (int ks = 0; ks < 16; ks++) {
            uint32_t ko = ks * 32;
            uint32_t a[2][4];
            LDSM4(a[0][0], a[0][1], a[0][2], a[0][3], aA0 + ko);
            LDSM4(a[1][0], a[1][1], a[1][2], a[1][3], aA1 + ko);
            #pragma unroll
            for (int p = 0; p < 2; p++) {
                uint32_t b0, b1, b2, b3;
                LDSM4(b0, b1, b2, b3, bB + p * (16 * RS) + ko);
                MMA16816(acc[0][2 * p],     a[0], b0, b1);
                MMA16816(acc[0][2 * p + 1], a[0], b2, b3);
                MMA16816(acc[1][2 * p],     a[1], b0, b1);
                MMA16816(acc[1][2 * p + 1], a[1], b2, b3);
            }
        }

        int cbase = ch * 128 + wn * 32 + (lane & 3) * 2;

        // ---- pass 1: per-row running max (transform acc -> v in place) ----
        #pragma unroll
        for (int im = 0; im < 2; im++) {
            #pragma unroll
            for (int h = 0; h < 2; h++) {
                float m = -3.0e38f;
                #pragma unroll
                for (int jn = 0; jn < 4; jn++) {
                    float v0 = fmaf(-2.0f, acc[im][jn][h * 2],     ceS[cbase + jn * 8]);
                    float v1 = fmaf(-2.0f, acc[im][jn][h * 2 + 1], ceS[cbase + jn * 8 + 1]);
                    acc[im][jn][h * 2] = v0;
                    acc[im][jn][h * 2 + 1] = v1;
                    m = fmaxf(m, fmaxf(v0, v1));
                }
                m = fmaxf(m, __shfl_xor_sync(0xffffffffu, m, 1));
                m = fmaxf(m, __shfl_xor_sync(0xffffffffu, m, 2));
                if ((lane & 3) == 0)
                    atomicMax(&rowBest[wm * 32 + im * 16 + h * 8 + (lane >> 2)], fmono(m));
            }
        }
        __syncthreads();

        // ---- pass 2: collect candidates v >= rowBest - MARGIN (superset-safe) ----
        #pragma unroll
        for (int im = 0; im < 2; im++) {
            #pragma unroll
            for (int h = 0; h < 2; h++) {
                int lrow = wm * 32 + im * 16 + h * 8 + (lane >> 2);
                float thr = funmono(rowBest[lrow]) - MARGIN;
                #pragma unroll
                for (int jn = 0; jn < 4; jn++) {
                    #pragma unroll
                    for (int q = 0; q < 2; q++) {
                        float v = acc[im][jn][h * 2 + q];
                        if (v >= thr) {
                            int pos = atomicAdd(&sCnt[lrow], 1);
                            if (pos < CAND) sCand[lrow * CAND + pos] = cbase + jn * 8 + q;
                        }
                    }
                }
            }
        }
        // rowBest only grows -> later (tighter) thresholds remain superset-safe

        if (ch < 3) {
            CP_WAIT0();
            __syncthreads();
        }
    }
    __syncthreads();

    // =============== fused epilogue: resolve + gather + loss + hist ===============
    float lossAcc = 0.0f;
    #pragma unroll 1
    for (int rr = 0; rr < 8; rr++) {
        int lrow = wid * 8 + rr;
        int row = rowBase + lrow;

        const float4* zp = (const float4*)(z + (size_t)row * DIMK);
        float4 a = zp[lane * 2], b = zp[lane * 2 + 1];

        int cnt = sCnt[lrow];
        int idx;
        if (cnt == 1) {
            idx = sCand[lrow * CAND];
        } else {
            float best = -3.0e38f;
            idx = NCODE;
            bool full = (cnt > CAND);
            int n = full ? NCODE : cnt;
            #pragma unroll 1
            for (int ci = 0; ci < n; ci++) {
                int c = full ? ci : sCand[lrow * CAND + ci];
                const float4* ep = (const float4*)(emb + (size_t)c * DIMK);
                float4 e0 = ep[lane * 2], e1 = ep[lane * 2 + 1];
                float s = a.x * e0.x + a.y * e0.y + a.z * e0.z + a.w * e0.w
                        + b.x * e1.x + b.y * e1.y + b.z * e1.z + b.w * e1.w;
                #pragma unroll
                for (int o = 16; o > 0; o >>= 1) s += __shfl_xor_sync(0xffffffffu, s, o);
                float sim = ceS[c] - 2.0f * s;
                if (sim > best || (sim == best && c < idx)) { best = sim; idx = c; }
            }
        }

        const float* er = emb + (size_t)idx * DIMK;
        float* oq = out + ZQ_OFF + (size_t)row * DIMK;
        float4 e0 = *(const float4*)(er + lane * 8);
        float4 e1 = *(const float4*)(er + lane * 8 + 4);
        *(float4*)(oq + lane * 8)     = e0;
        *(float4*)(oq + lane * 8 + 4) = e1;
        float d0 = e0.x - a.x, d1 = e0.y - a.y, d2 = e0.z - a.z, d3 = e0.w - a.w;
        float d4 = e1.x - b.x, d5 = e1.y - b.y, d6 = e1.z - b.z, d7 = e1.w - b.w;
        lossAcc += d0 * d0 + d1 * d1 + d2 * d2 + d3 * d3
                 + d4 * d4 + d5 * d5 + d6 * d6 + d7 * d7;

        if (lane == 0) {
            out[IDX_OFF + row] = (float)idx;
            atomicAdd(&out[HIST_OFF + idx], 1.0f);  // exact: integer-valued float adds
        }
    }

    // block-reduce loss partial (fixed order -> deterministic)
    #pragma unroll
    for (int o = 16; o > 0; o >>= 1) lossAcc += __shfl_down_sync(0xffffffffu, lossAcc, o);
    __shared__ float ws[16];
    if (lane == 0) ws[wid] = lossAcc;
    __syncthreads();
    if (tid == 0) {
        float t = 0.0f;
        #pragma unroll
        for (int i = 0; i < 16; i++) t += ws[i];
        g_part[blockIdx.x] = t;
    }
}

// ---------------- Kernel: finalize losses (fixed-pairing tree, deterministic) ----------------
__global__ __launch_bounds__(1024) void k_final(float* __restrict__ out) {
    cudaGridDependencySynchronize();   // k_mma's g_part writes visible
    __shared__ float ps[1024];
    int t = threadIdx.x;
    ps[t] = g_part[t];                 // NBLK == 1024, one partial per thread
    __syncthreads();
    #pragma unroll
    for (int s = 512; s > 0; s >>= 1) {   // fixed pairing every replay -> deterministic
        if (t < s) ps[t] += ps[t + s];
        __syncthreads();
    }
    if (t == 0) {
        float vq = ps[0] / 33554432.0f;   // N_ROWS * DIMK
        out[VQ_OFF] = vq;
        out[CM_OFF] = 0.25f * vq;
    }
}

// ---------------- Launch ----------------
extern "C" void kernel_launch(void* const* d_in, const int* in_sizes, int n_in,
                              void* d_out, int out_size) {
    const float* z   = (const float*)d_in[0];
    const float* emb = (const float*)d_in[1];
    float* out = (float*)d_out;

    cudaFuncSetAttribute(k_mma, cudaFuncAttributeMaxDynamicSharedMemorySize, SMEM_BYTES);

    k_prep<<<NCODE, 64>>>(emb, out);

    // k_mma: PDL-dependent on k_prep
    {
        cudaLaunchConfig_t cfg = {};
        cfg.gridDim = dim3(NBLK);
        cfg.blockDim = dim3(512);
        cfg.dynamicSmemBytes = SMEM_BYTES;
        cfg.stream = 0;
        cudaLaunchAttribute at[1];
        at[0].id = cudaLaunchAttributeProgrammaticStreamSerialization;
        at[0].val.programmaticStreamSerializationAllowed = 1;
        cfg.attrs = at;
        cfg.numAttrs = 1;
        cudaLaunchKernelEx(&cfg, k_mma, z, emb, out);
    }

    // k_final: PDL-dependent on k_mma (overlaps its launch setup with k_mma tail)
    {
        cudaLaunchConfig_t cfg = {};
        cfg.gridDim = dim3(1);
        cfg.blockDim = dim3(1024);
        cfg.dynamicSmemBytes = 0;
        cfg.stream = 0;
        cudaLaunchAttribute at[1];
        at[0].id = cudaLaunchAttributeProgrammaticStreamSerialization;
        at[0].val.programmaticStreamSerializationAllowed = 1;
        cfg.attrs = at;
        cfg.numAttrs = 1;
        cudaLaunchKernelEx(&cfg, k_final, out);
    }
}